// round 5
// baseline (speedup 1.0000x reference)
#include <cuda_runtime.h>
#include <cuda_bf16.h>
#include <stdint.h>

// Problem dims
#define B_    4096
#define S_    128
#define E_    1024
#define H1D   4096
#define H2D   2048
#define NCLS  3

// GEMM tiling: 128x128 CTA tile, 256 threads, warp grid 2(M) x 4(N), warp tile 64x32
#define BM 128
#define BN 128
#define BK 64
#define NST 2
#define A_TILE_B 16384                       // 128 rows * 128B (one of hi/lo)
#define B_TILE_B 16384                       // 128 rows * 128B
#define STAGE_B  (2*A_TILE_B + B_TILE_B)     // 49152
#define BIAS_B   1024
#define GEMM_DYN (BIAS_B + NST*STAGE_B)      // 99328

// ---------------- scratch (static device globals) ----------------
__device__ __nv_bfloat16 g_X2[(size_t)B_ * 2 * E_];      // pooled activations [hi|lo]
__device__ __nv_bfloat16 g_T1[(size_t)H1D * E_];         // ternary w1 bf16
__device__ float         g_Y1[(size_t)B_ * H1D];
__device__ __nv_bfloat16 g_H1[(size_t)B_ * 2 * H1D];     // h1 [hi|lo]
__device__ __nv_bfloat16 g_T2[(size_t)H2D * H1D];        // ternary w2 bf16
__device__ float         g_Y2[(size_t)B_ * H2D];
__device__ float         g_H2[(size_t)B_ * H2D];
__device__ float         g_T3[NCLS * H2D];
__device__ double        g_absum[3];
__device__ float         g_scales[3];

// ---------------- helpers ----------------
static __device__ __forceinline__ uint32_t smem_u32(const void* p) {
    return (uint32_t)__cvta_generic_to_shared(p);
}
static __device__ __forceinline__ void cp_async16(uint32_t s, const void* g) {
    asm volatile("cp.async.cg.shared.global [%0], [%1], 16;\n" :: "r"(s), "l"(g));
}

// ---------------- embedding gather + masked mean pool ----------------
__global__ void pool_kernel(const int* __restrict__ ids, const float* __restrict__ emb) {
    __shared__ int sid[S_];
    __shared__ int scnt;
    int b = blockIdx.x, t = threadIdx.x;   // 256 threads
    if (t == 0) scnt = 0;
    __syncthreads();
    if (t < S_) {
        int id = ids[(size_t)b * S_ + t];
        sid[t] = id;
        if (id != 0) atomicAdd(&scnt, 1);
    }
    __syncthreads();
    int d = t * 4;
    float a0 = 0.f, a1 = 0.f, a2 = 0.f, a3 = 0.f;
    for (int s = 0; s < S_; s++) {
        int id = sid[s];
        if (id != 0) {
            float4 v = *(const float4*)(emb + (size_t)id * E_ + d);
            a0 += v.x; a1 += v.y; a2 += v.z; a3 += v.w;
        }
    }
    int c = scnt;
    float inv = 1.0f / (float)(c > 0 ? c : 1);
    float x[4] = {a0 * inv, a1 * inv, a2 * inv, a3 * inv};
    __nv_bfloat16* dst = g_X2 + (size_t)b * 2 * E_;
#pragma unroll
    for (int j = 0; j < 4; j++) {
        __nv_bfloat16 hi = __float2bfloat16(x[j]);
        __nv_bfloat16 lo = __float2bfloat16(x[j] - __bfloat162float(hi));
        dst[d + j]      = hi;
        dst[E_ + d + j] = lo;
    }
}

// ---------------- scale computation ----------------
__global__ void zero_kernel() {
    if (threadIdx.x < 3) g_absum[threadIdx.x] = 0.0;
}

// blocks [0,1024) -> w1, [1024,2048) -> w2, 2048 -> w3
__global__ void absum_all_kernel(const float* __restrict__ w1,
                                 const float* __restrict__ w2,
                                 const float* __restrict__ w3) {
    __shared__ double red[256];
    const float* w; size_t n; int idx, bid, nb;
    if (blockIdx.x < 1024)      { w = w1; n = (size_t)H1D * E_;  idx = 0; bid = blockIdx.x;        nb = 1024; }
    else if (blockIdx.x < 2048) { w = w2; n = (size_t)H2D * H1D; idx = 1; bid = blockIdx.x - 1024; nb = 1024; }
    else                        { w = w3; n = NCLS * H2D;        idx = 2; bid = 0;                 nb = 1;    }
    double s = 0.0;
    for (size_t i = (size_t)bid * 256 + threadIdx.x; i < n; i += (size_t)nb * 256)
        s += (double)fabsf(w[i]);
    red[threadIdx.x] = s;
    __syncthreads();
    for (int o = 128; o > 0; o >>= 1) {
        if (threadIdx.x < o) red[threadIdx.x] += red[threadIdx.x + o];
        __syncthreads();
    }
    if (threadIdx.x == 0) atomicAdd(&g_absum[idx], red[0]);
}

__global__ void finalize_kernel() {
    if (threadIdx.x == 0) {
        g_scales[0] = (float)(g_absum[0] / (double)((size_t)H1D * E_));
        g_scales[1] = (float)(g_absum[1] / (double)((size_t)H2D * H1D));
        g_scales[2] = (float)(g_absum[2] / (double)(NCLS * H2D));
    }
}

// quantize all three weight tensors in one launch
__global__ void quant_all_kernel(const float* __restrict__ w1,
                                 const float* __restrict__ w2,
                                 const float* __restrict__ w3) {
    const int n1 = H1D * E_;
    const int n2 = H2D * H1D;
    const int n3 = NCLS * H2D;
    const float i0 = 1.0f / g_scales[0];
    const float i1 = 1.0f / g_scales[1];
    const float i2 = 1.0f / g_scales[2];
    const int total = n1 + n2 + n3;
    for (int i = blockIdx.x * 256 + threadIdx.x; i < total; i += gridDim.x * 256) {
        if (i < n1) {
            float v = rintf(fminf(fmaxf(w1[i] * i0, -1.0f), 1.0f));
            g_T1[i] = __float2bfloat16(v);
        } else if (i < n1 + n2) {
            int k = i - n1;
            float v = rintf(fminf(fmaxf(w2[k] * i1, -1.0f), 1.0f));
            g_T2[k] = __float2bfloat16(v);
        } else {
            int k = i - n1 - n2;
            g_T3[k] = rintf(fminf(fmaxf(w3[k] * i2, -1.0f), 1.0f));
        }
    }
}

// ---------------- bf16 mma.sync GEMM ----------------
// C[M,N] = scale * ((Ahi + Alo)[M,K] @ Bw[N,K]^T) + bias[n]
// A rows are [hi(K) | lo(K)] with stride 2K. Two accumulation passes share B frags.
__global__ __launch_bounds__(256)
void gemm_bf16(const __nv_bfloat16* __restrict__ A,
               const __nv_bfloat16* __restrict__ Bw,
               const float* __restrict__ bias,
               const float* __restrict__ scale_p,
               float* __restrict__ C, int N, int K) {
    extern __shared__ __align__(1024) char smem[];
    const uint32_t sb = smem_u32(smem) + BIAS_B;
    const int tid = threadIdx.x, lane = tid & 31, warp = tid >> 5;
    const int wm = warp & 1, wn = warp >> 1;      // 2 x 4 warps, warp tile 64x32
    const int bm = blockIdx.y * BM, bn = blockIdx.x * BN;
    const int KT = K / BK;
    const size_t Astride = 2 * (size_t)K;

    // cache bias tile (used only in epilogue, after syncs)
    for (int i = tid; i < BN; i += 256)
        *(float*)(smem + i * 4) = bias[bn + i];

    float acc[4][4][4];
#pragma unroll
    for (int i = 0; i < 4; i++)
#pragma unroll
        for (int j = 0; j < 4; j++)
#pragma unroll
            for (int v = 0; v < 4; v++) acc[i][j][v] = 0.f;

    auto load_stage = [&](int c) {
        const uint32_t base = sb + (uint32_t)(c & 1) * STAGE_B;
        const int k0 = c * BK;
        // A hi + lo: 128 rows x 8 chunks (16B) each
#pragma unroll
        for (int r = 0; r < 4; r++) {
            int idx = tid + r * 256;
            int row = idx >> 3, ch = idx & 7;
            uint32_t sw = row * 128 + ((ch ^ (row & 7)) << 4);
            const __nv_bfloat16* ga = A + (size_t)(bm + row) * Astride + k0 + ch * 8;
            cp_async16(base + sw, ga);
            cp_async16(base + A_TILE_B + sw, ga + K);
        }
        // B: 128 rows x 8 chunks
#pragma unroll
        for (int r = 0; r < 4; r++) {
            int idx = tid + r * 256;
            int row = idx >> 3, ch = idx & 7;
            uint32_t sw = row * 128 + ((ch ^ (row & 7)) << 4);
            cp_async16(base + 2 * A_TILE_B + sw,
                       Bw + (size_t)(bn + row) * K + k0 + ch * 8);
        }
        asm volatile("cp.async.commit_group;\n" ::: "memory");
    };

    load_stage(0);

    for (int c = 0; c < KT; ++c) {
        asm volatile("cp.async.wait_group 0;\n" ::: "memory");
        __syncthreads();
        if (c + 1 < KT) load_stage(c + 1);

        const uint32_t base  = sb + (uint32_t)(c & 1) * STAGE_B;
        const uint32_t Ahi_b = base;
        const uint32_t Alo_b = base + A_TILE_B;
        const uint32_t Bb    = base + 2 * A_TILE_B;

#pragma unroll
        for (int kk = 0; kk < 4; ++kk) {
            uint32_t b[4][2];
#pragma unroll
            for (int j = 0; j < 4; j++) {
                int row = wn * 32 + j * 8 + (lane & 7);
                int c2 = kk * 2 + ((lane >> 3) & 1);
                uint32_t addr = Bb + row * 128 + ((c2 ^ (row & 7)) << 4);
                asm volatile("ldmatrix.sync.aligned.m8n8.x2.shared.b16 {%0,%1}, [%2];\n"
                             : "=r"(b[j][0]), "=r"(b[j][1]) : "r"(addr));
            }
#pragma unroll
            for (int pass = 0; pass < 2; pass++) {
                const uint32_t Ab = pass ? Alo_b : Ahi_b;
                uint32_t a[4][4];
#pragma unroll
                for (int i = 0; i < 4; i++) {
                    int row = wm * 64 + i * 16 + (lane & 15);
                    int c2 = kk * 2 + (lane >> 4);
                    uint32_t addr = Ab + row * 128 + ((c2 ^ (row & 7)) << 4);
                    asm volatile("ldmatrix.sync.aligned.m8n8.x4.shared.b16 {%0,%1,%2,%3}, [%4];\n"
                                 : "=r"(a[i][0]), "=r"(a[i][1]), "=r"(a[i][2]), "=r"(a[i][3])
                                 : "r"(addr));
                }
#pragma unroll
                for (int i = 0; i < 4; i++)
#pragma unroll
                    for (int j = 0; j < 4; j++) {
                        asm volatile(
                            "mma.sync.aligned.m16n8k16.row.col.f32.bf16.bf16.f32 "
                            "{%0,%1,%2,%3}, {%4,%5,%6,%7}, {%8,%9}, {%0,%1,%2,%3};\n"
                            : "+f"(acc[i][j][0]), "+f"(acc[i][j][1]),
                              "+f"(acc[i][j][2]), "+f"(acc[i][j][3])
                            : "r"(a[i][0]), "r"(a[i][1]), "r"(a[i][2]), "r"(a[i][3]),
                              "r"(b[j][0]), "r"(b[j][1]));
                    }
            }
        }
    }

    const float s = *scale_p;
    const float* bsm = (const float*)smem;
#pragma unroll
    for (int i = 0; i < 4; i++)
#pragma unroll
        for (int j = 0; j < 4; j++) {
            int gm = bm + wm * 64 + i * 16 + (lane >> 2);
            int ln = wn * 32 + j * 8 + (lane & 3) * 2;
            int gn = bn + ln;
            float b0 = bsm[ln], b1 = bsm[ln + 1];
            C[(size_t)gm * N + gn]           = acc[i][j][0] * s + b0;
            C[(size_t)gm * N + gn + 1]       = acc[i][j][1] * s + b1;
            C[(size_t)(gm + 8) * N + gn]     = acc[i][j][2] * s + b0;
            C[(size_t)(gm + 8) * N + gn + 1] = acc[i][j][3] * s + b1;
        }
}

// ---------------- LayerNorm + exact GELU ----------------
template <int NE>
__global__ void ln_gelu_kernel(const float* __restrict__ Y,
                               const float* __restrict__ gam,
                               const float* __restrict__ bet,
                               int N,
                               __nv_bfloat16* __restrict__ Hdup,   // [row][2N] hi|lo or null
                               float* __restrict__ Hf) {           // [row][N] fp32 or null
    __shared__ float red[256];
    int row = blockIdx.x, t = threadIdx.x;
    const float* y = Y + (size_t)row * N;
    float v[NE];
    float s = 0.f;
#pragma unroll
    for (int i = 0; i < NE; i++) { v[i] = y[t + i * 256]; s += v[i]; }
    red[t] = s; __syncthreads();
    for (int o = 128; o > 0; o >>= 1) { if (t < o) red[t] += red[t + o]; __syncthreads(); }
    float mu = red[0] / (float)N;
    __syncthreads();
    float q = 0.f;
#pragma unroll
    for (int i = 0; i < NE; i++) { float d = v[i] - mu; q += d * d; }
    red[t] = q; __syncthreads();
    for (int o = 128; o > 0; o >>= 1) { if (t < o) red[t] += red[t + o]; __syncthreads(); }
    float rstd = rsqrtf(red[0] / (float)N + 1e-5f);
#pragma unroll
    for (int i = 0; i < NE; i++) {
        int col = t + i * 256;
        float h = (v[i] - mu) * rstd * gam[col] + bet[col];
        float ge = 0.5f * h * (1.0f + erff(h * 0.70710678118654752440f));
        if (Hdup) {
            __nv_bfloat16 hi = __float2bfloat16(ge);
            __nv_bfloat16 lo = __float2bfloat16(ge - __bfloat162float(hi));
            Hdup[(size_t)row * 2 * N + col]     = hi;
            Hdup[(size_t)row * 2 * N + N + col] = lo;
        }
        if (Hf) Hf[(size_t)row * N + col] = ge;
    }
}

// ---------------- final tiny layer (fp32) ----------------
__global__ void final_kernel(const float* __restrict__ b3, float* __restrict__ out) {
    __shared__ float red[NCLS][128];
    int row = blockIdx.x, t = threadIdx.x;   // 128 threads
    const float* h = g_H2 + (size_t)row * H2D;
    float a0 = 0.f, a1 = 0.f, a2 = 0.f;
    for (int k = t; k < H2D; k += 128) {
        float hv = h[k];
        a0 += hv * g_T3[k];
        a1 += hv * g_T3[H2D + k];
        a2 += hv * g_T3[2 * H2D + k];
    }
    red[0][t] = a0; red[1][t] = a1; red[2][t] = a2;
    __syncthreads();
    for (int o = 64; o > 0; o >>= 1) {
        if (t < o) {
            red[0][t] += red[0][t + o];
            red[1][t] += red[1][t + o];
            red[2][t] += red[2][t + o];
        }
        __syncthreads();
    }
    if (t < NCLS) out[row * NCLS + t] = g_scales[2] * red[t][0] + b3[t];
}

// ---------------- launch ----------------
extern "C" void kernel_launch(void* const* d_in, const int* in_sizes, int n_in,
                              void* d_out, int out_size) {
    const int*   ids = (const int*)d_in[0];
    const float* emb = (const float*)d_in[1];
    const float* w1  = (const float*)d_in[2];
    const float* b1  = (const float*)d_in[3];
    const float* w2  = (const float*)d_in[4];
    const float* b2  = (const float*)d_in[5];
    const float* w3  = (const float*)d_in[6];
    const float* b3  = (const float*)d_in[7];
    const float* g1  = (const float*)d_in[8];
    const float* be1 = (const float*)d_in[9];
    const float* g2  = (const float*)d_in[10];
    const float* be2 = (const float*)d_in[11];
    float* out = (float*)d_out;

    void *pX2, *pT1, *pY1, *pH1, *pT2, *pY2, *pH2, *pSc;
    cudaGetSymbolAddress(&pX2, g_X2);
    cudaGetSymbolAddress(&pT1, g_T1);
    cudaGetSymbolAddress(&pY1, g_Y1);
    cudaGetSymbolAddress(&pH1, g_H1);
    cudaGetSymbolAddress(&pT2, g_T2);
    cudaGetSymbolAddress(&pY2, g_Y2);
    cudaGetSymbolAddress(&pH2, g_H2);
    cudaGetSymbolAddress(&pSc, g_scales);

    cudaFuncSetAttribute(gemm_bf16, cudaFuncAttributeMaxDynamicSharedMemorySize, GEMM_DYN);

    // launches 1-5: pool + scales + quant (gemm1 is launch #6 for ncu -s 5 -c 1)
    pool_kernel<<<B_, 256>>>(ids, emb);
    zero_kernel<<<1, 32>>>();
    absum_all_kernel<<<2049, 256>>>(w1, w2, w3);
    finalize_kernel<<<1, 32>>>();
    quant_all_kernel<<<4096, 256>>>(w1, w2, w3);

    // 6) layer 1 GEMM: Y1 = s1*(X2 @ T1^T) + b1
    {
        dim3 grid(H1D / BN, B_ / BM);   // (32, 32)
        gemm_bf16<<<grid, 256, GEMM_DYN>>>((const __nv_bfloat16*)pX2, (const __nv_bfloat16*)pT1,
                                           b1, (const float*)pSc + 0, (float*)pY1, H1D, E_);
    }
    ln_gelu_kernel<16><<<B_, 256>>>((const float*)pY1, g1, be1, H1D,
                                    (__nv_bfloat16*)pH1, nullptr);

    // layer 2 GEMM: Y2 = s2*(H1 @ T2^T) + b2
    {
        dim3 grid(H2D / BN, B_ / BM);   // (16, 32)
        gemm_bf16<<<grid, 256, GEMM_DYN>>>((const __nv_bfloat16*)pH1, (const __nv_bfloat16*)pT2,
                                           b2, (const float*)pSc + 1, (float*)pY2, H2D, H1D);
    }
    ln_gelu_kernel<8><<<B_, 256>>>((const float*)pY2, g2, be2, H2D,
                                   nullptr, (float*)pH2);

    // final tiny layer
    final_kernel<<<B_, 128>>>(b3, out);
}

// round 8
// speedup vs baseline: 1.4128x; 1.4128x over previous
#include <cuda_runtime.h>
#include <cuda_bf16.h>
#include <stdint.h>

// Problem dims
#define B_    4096
#define S_    128
#define E_    1024
#define H1D   4096
#define H2D   2048
#define NCLS  3

// GEMM tiling: 128x128 CTA tile, 256 threads, warp grid 2(M) x 4(N), warp tile 64x32
#define BM 128
#define BN 128
#define BK 64
#define NST 2
#define A_TILE_B 16384                       // 128 rows * 128B (one of hi/lo)
#define B_TILE_B 16384                       // 128 rows * 128B
#define STAGE_B  (2*A_TILE_B + B_TILE_B)     // 49152
#define BIAS_B   1024
#define GEMM_DYN (BIAS_B + NST*STAGE_B)      // 99328

// ---------------- scratch (static device globals) ----------------
__device__ __nv_bfloat16 g_X2[(size_t)B_ * 2 * E_];      // pooled activations [hi|lo]
__device__ __nv_bfloat16 g_T1[(size_t)H1D * E_];         // ternary w1 bf16
__device__ float         g_Y1[(size_t)B_ * H1D];
__device__ __nv_bfloat16 g_H1[(size_t)B_ * 2 * H1D];     // h1 [hi|lo]
__device__ __nv_bfloat16 g_T2[(size_t)H2D * H1D];        // ternary w2 bf16
__device__ float         g_Y2[(size_t)B_ * H2D];
__device__ float         g_H2[(size_t)B_ * H2D];
__device__ float         g_T3[NCLS * H2D];
__device__ double        g_absum[3];
__device__ float         g_scales[3];

// ---------------- helpers ----------------
static __device__ __forceinline__ uint32_t smem_u32(const void* p) {
    return (uint32_t)__cvta_generic_to_shared(p);
}
static __device__ __forceinline__ void cp_async16(uint32_t s, const void* g) {
    asm volatile("cp.async.cg.shared.global [%0], [%1], 16;\n" :: "r"(s), "l"(g));
}

// ---------------- embedding gather + masked mean pool (also zeroes g_absum) ------
__global__ void pool_kernel(const int* __restrict__ ids, const float* __restrict__ emb) {
    __shared__ int sid[S_];
    __shared__ int scnt;
    int b = blockIdx.x, t = threadIdx.x;   // 256 threads
    if (b == 0 && t < 3) g_absum[t] = 0.0;   // stream-ordered before absum kernel
    if (t == 0) scnt = 0;
    __syncthreads();
    if (t < S_) {
        int id = ids[(size_t)b * S_ + t];
        sid[t] = id;
        if (id != 0) atomicAdd(&scnt, 1);
    }
    __syncthreads();
    int d = t * 4;
    float a0 = 0.f, a1 = 0.f, a2 = 0.f, a3 = 0.f;
    for (int s = 0; s < S_; s++) {
        int id = sid[s];
        if (id != 0) {
            float4 v = *(const float4*)(emb + (size_t)id * E_ + d);
            a0 += v.x; a1 += v.y; a2 += v.z; a3 += v.w;
        }
    }
    int c = scnt;
    float inv = 1.0f / (float)(c > 0 ? c : 1);
    float x[4] = {a0 * inv, a1 * inv, a2 * inv, a3 * inv};
    __nv_bfloat16* dst = g_X2 + (size_t)b * 2 * E_;
#pragma unroll
    for (int j = 0; j < 4; j++) {
        __nv_bfloat16 hi = __float2bfloat16(x[j]);
        __nv_bfloat16 lo = __float2bfloat16(x[j] - __bfloat162float(hi));
        dst[d + j]      = hi;
        dst[E_ + d + j] = lo;
    }
}

// ---------------- abs-sum reduction ----------------
// blocks [0,1024) -> w1, [1024,2048) -> w2, 2048 -> w3
__global__ void absum_all_kernel(const float* __restrict__ w1,
                                 const float* __restrict__ w2,
                                 const float* __restrict__ w3) {
    __shared__ double red[256];
    const float* w; size_t n; int idx, bid, nb;
    if (blockIdx.x < 1024)      { w = w1; n = (size_t)H1D * E_;  idx = 0; bid = blockIdx.x;        nb = 1024; }
    else if (blockIdx.x < 2048) { w = w2; n = (size_t)H2D * H1D; idx = 1; bid = blockIdx.x - 1024; nb = 1024; }
    else                        { w = w3; n = NCLS * H2D;        idx = 2; bid = 0;                 nb = 1;    }
    double s = 0.0;
    for (size_t i = (size_t)bid * 256 + threadIdx.x; i < n; i += (size_t)nb * 256)
        s += (double)fabsf(w[i]);
    red[threadIdx.x] = s;
    __syncthreads();
    for (int o = 128; o > 0; o >>= 1) {
        if (threadIdx.x < o) red[threadIdx.x] += red[threadIdx.x + o];
        __syncthreads();
    }
    if (threadIdx.x == 0) atomicAdd(&g_absum[idx], red[0]);
}

// quantize all three weight tensors; derives scales from g_absum (finalize folded in)
__global__ void quant_all_kernel(const float* __restrict__ w1,
                                 const float* __restrict__ w2,
                                 const float* __restrict__ w3) {
    const int n1 = H1D * E_;
    const int n2 = H2D * H1D;
    const int n3 = NCLS * H2D;
    const float s0 = (float)(g_absum[0] / (double)n1);
    const float s1 = (float)(g_absum[1] / (double)n2);
    const float s2 = (float)(g_absum[2] / (double)n3);
    if (blockIdx.x == 0 && threadIdx.x < 3)
        g_scales[threadIdx.x] = (threadIdx.x == 0) ? s0 : (threadIdx.x == 1 ? s1 : s2);
    const float i0 = 1.0f / s0;
    const float i1 = 1.0f / s1;
    const float i2 = 1.0f / s2;
    const int total = n1 + n2 + n3;
    for (int i = blockIdx.x * 256 + threadIdx.x; i < total; i += gridDim.x * 256) {
        if (i < n1) {
            float v = rintf(fminf(fmaxf(w1[i] * i0, -1.0f), 1.0f));
            g_T1[i] = __float2bfloat16(v);
        } else if (i < n1 + n2) {
            int k = i - n1;
            float v = rintf(fminf(fmaxf(w2[k] * i1, -1.0f), 1.0f));
            g_T2[k] = __float2bfloat16(v);
        } else {
            int k = i - n1 - n2;
            g_T3[k] = rintf(fminf(fmaxf(w3[k] * i2, -1.0f), 1.0f));
        }
    }
}

// ---------------- bf16 mma.sync GEMM ----------------
// C[M,N] = scale * ((Ahi + Alo)[M,K] @ Bw[N,K]^T) + bias[n]
// A rows are [hi(K) | lo(K)] with stride 2K. Two accumulation passes share B frags.
// __launch_bounds__(256, 2): cap regs at 128/thread so 2 CTAs/SM co-reside.
__global__ __launch_bounds__(256, 2)
void gemm_bf16(const __nv_bfloat16* __restrict__ A,
               const __nv_bfloat16* __restrict__ Bw,
               const float* __restrict__ bias,
               const float* __restrict__ scale_p,
               float* __restrict__ C, int N, int K) {
    extern __shared__ __align__(1024) char smem[];
    const uint32_t sb = smem_u32(smem) + BIAS_B;
    const int tid = threadIdx.x, lane = tid & 31, warp = tid >> 5;
    const int wm = warp & 1, wn = warp >> 1;      // 2 x 4 warps, warp tile 64x32
    const int bm = blockIdx.y * BM, bn = blockIdx.x * BN;
    const int KT = K / BK;
    const size_t Astride = 2 * (size_t)K;

    // cache bias tile (used only in epilogue, after syncs)
    for (int i = tid; i < BN; i += 256)
        *(float*)(smem + i * 4) = bias[bn + i];

    float acc[4][4][4];
#pragma unroll
    for (int i = 0; i < 4; i++)
#pragma unroll
        for (int j = 0; j < 4; j++)
#pragma unroll
            for (int v = 0; v < 4; v++) acc[i][j][v] = 0.f;

    auto load_stage = [&](int c) {
        const uint32_t base = sb + (uint32_t)(c & 1) * STAGE_B;
        const int k0 = c * BK;
        // A hi + lo: 128 rows x 8 chunks (16B) each
#pragma unroll
        for (int r = 0; r < 4; r++) {
            int idx = tid + r * 256;
            int row = idx >> 3, ch = idx & 7;
            uint32_t sw = row * 128 + ((ch ^ (row & 7)) << 4);
            const __nv_bfloat16* ga = A + (size_t)(bm + row) * Astride + k0 + ch * 8;
            cp_async16(base + sw, ga);
            cp_async16(base + A_TILE_B + sw, ga + K);
        }
        // B: 128 rows x 8 chunks
#pragma unroll
        for (int r = 0; r < 4; r++) {
            int idx = tid + r * 256;
            int row = idx >> 3, ch = idx & 7;
            uint32_t sw = row * 128 + ((ch ^ (row & 7)) << 4);
            cp_async16(base + 2 * A_TILE_B + sw,
                       Bw + (size_t)(bn + row) * K + k0 + ch * 8);
        }
        asm volatile("cp.async.commit_group;\n" ::: "memory");
    };

    load_stage(0);

    for (int c = 0; c < KT; ++c) {
        asm volatile("cp.async.wait_group 0;\n" ::: "memory");
        __syncthreads();
        if (c + 1 < KT) load_stage(c + 1);

        const uint32_t base  = sb + (uint32_t)(c & 1) * STAGE_B;
        const uint32_t Ahi_b = base;
        const uint32_t Alo_b = base + A_TILE_B;
        const uint32_t Bb    = base + 2 * A_TILE_B;

#pragma unroll
        for (int kk = 0; kk < 4; ++kk) {
            uint32_t b[4][2];
#pragma unroll
            for (int j = 0; j < 4; j++) {
                int row = wn * 32 + j * 8 + (lane & 7);
                int c2 = kk * 2 + ((lane >> 3) & 1);
                uint32_t addr = Bb + row * 128 + ((c2 ^ (row & 7)) << 4);
                asm volatile("ldmatrix.sync.aligned.m8n8.x2.shared.b16 {%0,%1}, [%2];\n"
                             : "=r"(b[j][0]), "=r"(b[j][1]) : "r"(addr));
            }
#pragma unroll
            for (int pass = 0; pass < 2; pass++) {
                const uint32_t Ab = pass ? Alo_b : Ahi_b;
                uint32_t a[4][4];
#pragma unroll
                for (int i = 0; i < 4; i++) {
                    int row = wm * 64 + i * 16 + (lane & 15);
                    int c2 = kk * 2 + (lane >> 4);
                    uint32_t addr = Ab + row * 128 + ((c2 ^ (row & 7)) << 4);
                    asm volatile("ldmatrix.sync.aligned.m8n8.x4.shared.b16 {%0,%1,%2,%3}, [%4];\n"
                                 : "=r"(a[i][0]), "=r"(a[i][1]), "=r"(a[i][2]), "=r"(a[i][3])
                                 : "r"(addr));
                }
#pragma unroll
                for (int i = 0; i < 4; i++)
#pragma unroll
                    for (int j = 0; j < 4; j++) {
                        asm volatile(
                            "mma.sync.aligned.m16n8k16.row.col.f32.bf16.bf16.f32 "
                            "{%0,%1,%2,%3}, {%4,%5,%6,%7}, {%8,%9}, {%0,%1,%2,%3};\n"
                            : "+f"(acc[i][j][0]), "+f"(acc[i][j][1]),
                              "+f"(acc[i][j][2]), "+f"(acc[i][j][3])
                            : "r"(a[i][0]), "r"(a[i][1]), "r"(a[i][2]), "r"(a[i][3]),
                              "r"(b[j][0]), "r"(b[j][1]));
                    }
            }
        }
    }

    const float s = *scale_p;
    const float* bsm = (const float*)smem;
#pragma unroll
    for (int i = 0; i < 4; i++)
#pragma unroll
        for (int j = 0; j < 4; j++) {
            int gm = bm + wm * 64 + i * 16 + (lane >> 2);
            int ln = wn * 32 + j * 8 + (lane & 3) * 2;
            int gn = bn + ln;
            float b0 = bsm[ln], b1 = bsm[ln + 1];
            C[(size_t)gm * N + gn]           = acc[i][j][0] * s + b0;
            C[(size_t)gm * N + gn + 1]       = acc[i][j][1] * s + b1;
            C[(size_t)(gm + 8) * N + gn]     = acc[i][j][2] * s + b0;
            C[(size_t)(gm + 8) * N + gn + 1] = acc[i][j][3] * s + b1;
        }
}

// ---------------- LayerNorm + exact GELU ----------------
template <int NE>
__global__ void ln_gelu_kernel(const float* __restrict__ Y,
                               const float* __restrict__ gam,
                               const float* __restrict__ bet,
                               int N,
                               __nv_bfloat16* __restrict__ Hdup,   // [row][2N] hi|lo or null
                               float* __restrict__ Hf) {           // [row][N] fp32 or null
    __shared__ float red[256];
    int row = blockIdx.x, t = threadIdx.x;
    const float* y = Y + (size_t)row * N;
    float v[NE];
    float s = 0.f;
#pragma unroll
    for (int i = 0; i < NE; i++) { v[i] = y[t + i * 256]; s += v[i]; }
    red[t] = s; __syncthreads();
    for (int o = 128; o > 0; o >>= 1) { if (t < o) red[t] += red[t + o]; __syncthreads(); }
    float mu = red[0] / (float)N;
    __syncthreads();
    float q = 0.f;
#pragma unroll
    for (int i = 0; i < NE; i++) { float d = v[i] - mu; q += d * d; }
    red[t] = q; __syncthreads();
    for (int o = 128; o > 0; o >>= 1) { if (t < o) red[t] += red[t + o]; __syncthreads(); }
    float rstd = rsqrtf(red[0] / (float)N + 1e-5f);
#pragma unroll
    for (int i = 0; i < NE; i++) {
        int col = t + i * 256;
        float h = (v[i] - mu) * rstd * gam[col] + bet[col];
        float ge = 0.5f * h * (1.0f + erff(h * 0.70710678118654752440f));
        if (Hdup) {
            __nv_bfloat16 hi = __float2bfloat16(ge);
            __nv_bfloat16 lo = __float2bfloat16(ge - __bfloat162float(hi));
            Hdup[(size_t)row * 2 * N + col]     = hi;
            Hdup[(size_t)row * 2 * N + N + col] = lo;
        }
        if (Hf) Hf[(size_t)row * N + col] = ge;
    }
}

// ---------------- final tiny layer (fp32) ----------------
__global__ void final_kernel(const float* __restrict__ b3, float* __restrict__ out) {
    __shared__ float red[NCLS][128];
    int row = blockIdx.x, t = threadIdx.x;   // 128 threads
    const float* h = g_H2 + (size_t)row * H2D;
    float a0 = 0.f, a1 = 0.f, a2 = 0.f;
    for (int k = t; k < H2D; k += 128) {
        float hv = h[k];
        a0 += hv * g_T3[k];
        a1 += hv * g_T3[H2D + k];
        a2 += hv * g_T3[2 * H2D + k];
    }
    red[0][t] = a0; red[1][t] = a1; red[2][t] = a2;
    __syncthreads();
    for (int o = 64; o > 0; o >>= 1) {
        if (t < o) {
            red[0][t] += red[0][t + o];
            red[1][t] += red[1][t + o];
            red[2][t] += red[2][t + o];
        }
        __syncthreads();
    }
    if (t < NCLS) out[row * NCLS + t] = g_scales[2] * red[t][0] + b3[t];
}

// ---------------- launch ----------------
extern "C" void kernel_launch(void* const* d_in, const int* in_sizes, int n_in,
                              void* d_out, int out_size) {
    const int*   ids = (const int*)d_in[0];
    const float* emb = (const float*)d_in[1];
    const float* w1  = (const float*)d_in[2];
    const float* b1  = (const float*)d_in[3];
    const float* w2  = (const float*)d_in[4];
    const float* b2  = (const float*)d_in[5];
    const float* w3  = (const float*)d_in[6];
    const float* b3  = (const float*)d_in[7];
    const float* g1  = (const float*)d_in[8];
    const float* be1 = (const float*)d_in[9];
    const float* g2  = (const float*)d_in[10];
    const float* be2 = (const float*)d_in[11];
    float* out = (float*)d_out;

    void *pX2, *pT1, *pY1, *pH1, *pT2, *pY2, *pH2, *pSc;
    cudaGetSymbolAddress(&pX2, g_X2);
    cudaGetSymbolAddress(&pT1, g_T1);
    cudaGetSymbolAddress(&pY1, g_Y1);
    cudaGetSymbolAddress(&pH1, g_H1);
    cudaGetSymbolAddress(&pT2, g_T2);
    cudaGetSymbolAddress(&pY2, g_Y2);
    cudaGetSymbolAddress(&pH2, g_H2);
    cudaGetSymbolAddress(&pSc, g_scales);

    cudaFuncSetAttribute(gemm_bf16, cudaFuncAttributeMaxDynamicSharedMemorySize, GEMM_DYN);

    // launches 1-3: pool(+zero) + absum + quant(+finalize); gemm1 is my 4th launch
    pool_kernel<<<B_, 256>>>(ids, emb);
    absum_all_kernel<<<2049, 256>>>(w1, w2, w3);
    quant_all_kernel<<<4096, 256>>>(w1, w2, w3);

    // 4) layer 1 GEMM: Y1 = s1*(X2 @ T1^T) + b1
    {
        dim3 grid(H1D / BN, B_ / BM);   // (32, 32)
        gemm_bf16<<<grid, 256, GEMM_DYN>>>((const __nv_bfloat16*)pX2, (const __nv_bfloat16*)pT1,
                                           b1, (const float*)pSc + 0, (float*)pY1, H1D, E_);
    }
    ln_gelu_kernel<16><<<B_, 256>>>((const float*)pY1, g1, be1, H1D,
                                    (__nv_bfloat16*)pH1, nullptr);

    // layer 2 GEMM: Y2 = s2*(H1 @ T2^T) + b2
    {
        dim3 grid(H2D / BN, B_ / BM);   // (16, 32)
        gemm_bf16<<<grid, 256, GEMM_DYN>>>((const __nv_bfloat16*)pH1, (const __nv_bfloat16*)pT2,
                                           b2, (const float*)pSc + 1, (float*)pY2, H2D, H1D);
    }
    ln_gelu_kernel<8><<<B_, 256>>>((const float*)pY2, g2, be2, H2D,
                                   nullptr, (float*)pH2);

    // final tiny layer
    final_kernel<<<B_, 128>>>(b3, out);
}